// round 12
// baseline (speedup 1.0000x reference)
#include <cuda_runtime.h>

#define HW   4096
#define C    128
#define CR   32
#define G    8
#define CG   16
#define KK   49
#define KKG  392
#define NPX  16384   // B * H * W
#define NCTA 148     // <= SM count on B300/GB300 -> all CTAs co-resident

typedef unsigned long long u64;

// ---- packed f32x2 helpers (sm_103a) ---------------------------------------
__device__ __forceinline__ u64 pack2(float x, float y) {
    u64 r; asm("mov.b64 %0, {%1, %2};" : "=l"(r) : "f"(x), "f"(y)); return r;
}
__device__ __forceinline__ void unpack2(u64 v, float& x, float& y) {
    asm("mov.b64 {%0, %1}, %2;" : "=f"(x), "=f"(y) : "l"(v));
}
__device__ __forceinline__ void ffma2(u64& d, u64 a, u64 b) {
    asm("fma.rn.f32x2 %0, %1, %2, %0;" : "+l"(d) : "l"(a), "l"(b));
}

// Scratch + sync flags
__device__ __align__(16) float g_red[CR * NPX];        // [k][px]  k-major
__device__ __align__(16) float g_ker[4 * KKG * HW];    // [b][392][hw]
__device__ int g_rflag[256];   // reduce tile done flags (64 px each)
__device__ int g_scnt[64];     // span px-tile (256 px) completion counters (target 7)

__global__ void k_zero_flags() {
    int t = threadIdx.x;
    if (t < 256) g_rflag[t] = 0;
    if (t < 64)  g_scnt[t]  = 0;
}

// ---------------------------------------------------------------------------
// One persistent kernel: 148 CTAs x 256 threads, dynamic smem (union).
//   Phase 1 (reduce): 256 units of 64 px      -> sets g_rflag[u]
//   Phase 2 (span):   448 units (64 px-tiles x 7 o-tiles), spins on 4 rflags
//                     -> increments g_scnt[px_tile]
//   Phase 3 (inv):    256 units (32x16 px x (b,g)), spins on 4 scnt == 7
// ---------------------------------------------------------------------------
extern "C" __global__ void k_all(const float* __restrict__ x,
                                 const float* __restrict__ wr,
                                 const float* __restrict__ br,
                                 const float* __restrict__ wsp,
                                 const float* __restrict__ bs,
                                 float* __restrict__ out) {
    extern __shared__ char smem[];
    const int tid = threadIdx.x;
    const int bid = blockIdx.x;
    const int nb  = gridDim.x;

    // ================= Phase 1: reduce =================
    {
        u64* xsd = (u64*)smem;             // [128 c][32 px-pairs]  32 KB
        u64* wsd = xsd + C * 32;           // [128 c][33 (32 o dup)] 33.8 KB
        const int lane = tid & 31, warp = tid >> 5, wo = warp * 4;

        // stage duplicated w_reduce once (shared by all units)
#pragma unroll
        for (int l = 0; l < 16; l++) {
            int idx = tid + l * 256;               // 4096 = 32 o * 128 c
            int c = idx & 127, o = idx >> 7;
            float v = wr[o * C + c];
            wsd[c * 33 + o] = pack2(v, v);
        }

        for (int u = bid; u < 256; u += nb) {
            const int px0 = u * 64, b = px0 >> 12, hw0 = px0 & 4095;
            const float* xb = x + (size_t)b * C * HW + hw0;
            __syncthreads();                        // protect xsd reuse (+ wsd vis)
#pragma unroll
            for (int l = 0; l < 16; l++) {
                int idx = tid + l * 256;            // 4096 = 128 c * 32 pairs
                int c = idx >> 5, p2 = idx & 31;
                float2 v = *(const float2*)&xb[(size_t)c * HW + 2 * p2];
                xsd[c * 32 + p2] = pack2(v.x, v.y);
            }
            __syncthreads();

            u64 acc[4];
#pragma unroll
            for (int j = 0; j < 4; j++) {
                float bj = br[wo + j];
                acc[j] = pack2(bj, bj);
            }
#pragma unroll 8
            for (int k = 0; k < C; k++) {
                const u64 a = xsd[k * 32 + lane];
#pragma unroll
                for (int j = 0; j < 4; j++)
                    ffma2(acc[j], a, wsd[k * 33 + wo + j]);
            }
#pragma unroll
            for (int j = 0; j < 4; j++) {
                float f0, f1; unpack2(acc[j], f0, f1);
                *(float2*)&g_red[(size_t)(wo + j) * NPX + px0 + 2 * lane] =
                    make_float2(f0, f1);
            }
            __threadfence();
            __syncthreads();
            if (tid == 0) atomicExch(&g_rflag[u], 1);
        }
        __syncthreads();   // done with reduce smem layout
    }

    // ================= Phase 2: span =================
    {
        float* rs  = (float*)smem;                     // [32 k][258 px] 33 KB
        u64*   wsd = (u64*)(smem + CR * 258 * 4);      // [56 o][32 k] dup, 14 KB
        const int lane = tid & 31, warp = tid >> 5;

        for (int u = bid; u < 448; u += nb) {
            const int pt = u & 63, ot = u >> 6;
            const int px0 = pt * 256, o0 = ot * 56;
            const int b = px0 >> 12, hw0 = px0 & 4095;

            if (tid < 4) {
                volatile int* f = g_rflag + 4 * pt;
                while (f[tid] == 0) __nanosleep(64);
                __threadfence();
            }
            __syncthreads();     // also protects smem reuse across units

#pragma unroll
            for (int l = 0; l < 32; l++) {
                int idx = tid + l * 256;               // 8192 = 32 k * 256 px
                int k = idx >> 8, px = idx & 255;
                rs[k * 258 + px] = g_red[(size_t)k * NPX + px0 + px];
            }
#pragma unroll
            for (int l = 0; l < 7; l++) {
                int idx = tid + l * 256;               // 1792 = 56 o * 32 k
                float v = wsp[o0 * 32 + idx];
                wsd[idx] = pack2(v, v);
            }
            __syncthreads();

            u64 acc[4][7] = {};
#pragma unroll
            for (int k = 0; k < 32; k++) {
                u64 a[4];
#pragma unroll
                for (int v = 0; v < 4; v++)
                    a[v] = *(const u64*)&rs[k * 258 + 2 * lane + 64 * v];
#pragma unroll
                for (int j = 0; j < 7; j++) {
                    const u64 b2 = wsd[(warp * 7 + j) * 32 + k];  // uniform bcast
#pragma unroll
                    for (int v = 0; v < 4; v++) ffma2(acc[v][j], a[v], b2);
                }
            }
#pragma unroll
            for (int j = 0; j < 7; j++) {
                const int o = o0 + warp * 7 + j;
                const float bias = bs[o];
                float* kp = g_ker + ((size_t)b * KKG + o) * HW + hw0;
#pragma unroll
                for (int v = 0; v < 4; v++) {
                    float f0, f1; unpack2(acc[v][j], f0, f1);
                    *(float2*)&kp[2 * lane + 64 * v] =
                        make_float2(f0 + bias, f1 + bias);
                }
            }
            __threadfence();
            __syncthreads();
            if (tid == 0) atomicAdd(&g_scnt[pt], 1);
        }
        __syncthreads();   // done with span smem layout
    }

    // ================= Phase 3: involution =================
    {
        float* xsb = (float*)smem;   // [2 buf][2 ch][28 r][48 c] = 21.5 KB
        const int tx = tid & 15, ty = tid >> 4;

        for (int u = bid; u < 256; u += nb) {
            const int ixx = u & 1, iy = (u >> 1) & 3, bg = u >> 3;
            const int b = bg >> 3, g = bg & 7;
            const int tx0 = ixx * 32, ty0 = iy * 16;
            const int s0 = b * 16 + iy * 4;
            const int pix = (ty0 + ty) * 64 + tx0 + 2 * tx;

            if (tid < 4) {
                volatile int* f = g_scnt + s0;
                while (f[tid] < 7) __nanosleep(64);
                __threadfence();
            }
            __syncthreads();     // also protects smem reuse across units

            // 49 per-pixel kernel pairs -> registers (coalesced LDG.64)
            const float* kb = g_ker + ((size_t)b * KKG + g * KK) * HW + pix;
            u64 kreg[49];
#pragma unroll
            for (int kk = 0; kk < 49; kk++)
                kreg[kk] = *(const u64*)&kb[(size_t)kk * HW];

            const float* xb = x + ((size_t)b * C + g * CG) * HW;
            float* ob = out + ((size_t)b * C + g * CG) * HW + pix;

            // prime buffer 0 with channels 0,1
#pragma unroll
            for (int cc = 0; cc < 2; cc++) {
                const float* xc = xb + (size_t)cc * HW;
#pragma unroll
                for (int l = 0; l < 5; l++) {
                    int idx = tid + l * 256;
                    if (idx < 28 * 44) {
                        int r    = idx / 44;
                        int ccol = idx - r * 44;
                        int gy = ty0 - 6 + r, gx = tx0 - 6 + ccol;
                        float v = 0.f;
                        if (gy >= 0 && gy < 64 && gx >= 0 && gx < 64)
                            v = xc[gy * 64 + gx];
                        xsb[(cc * 28 + r) * 48 + ccol] = v;
                    }
                }
            }
            __syncthreads();

            for (int rnd = 0; rnd < 8; rnd++) {
                const int cur = rnd & 1;
                const int c0  = rnd * 2;

                float pf[10];
                if (rnd < 7) {
#pragma unroll
                    for (int cc = 0; cc < 2; cc++) {
                        const float* xc = xb + (size_t)(c0 + 2 + cc) * HW;
#pragma unroll
                        for (int l = 0; l < 5; l++) {
                            int idx = tid + l * 256;
                            float v = 0.f;
                            if (idx < 28 * 44) {
                                int r    = idx / 44;
                                int ccol = idx - r * 44;
                                int gy = ty0 - 6 + r, gx = tx0 - 6 + ccol;
                                if (gy >= 0 && gy < 64 && gx >= 0 && gx < 64)
                                    v = xc[gy * 64 + gx];
                            }
                            pf[cc * 5 + l] = v;
                        }
                    }
                }

#pragma unroll
                for (int cc = 0; cc < 2; cc++) {
                    u64 a0 = 0, a1 = 0;
                    const float* base = &xsb[((cur * 2 + cc) * 28) * 48];
#pragma unroll
                    for (int i = 0; i < 7; i++)
#pragma unroll
                        for (int j = 0; j < 7; j++) {
                            const int t = i * 7 + j;
                            const u64 v = *(const u64*)
                                &base[(ty + 2 * i) * 48 + 2 * tx + 2 * j];
                            if (t & 1) ffma2(a1, v, kreg[t]);
                            else       ffma2(a0, v, kreg[t]);
                        }
                    float e0, e1, o0v, o1v;
                    unpack2(a0, e0, e1); unpack2(a1, o0v, o1v);
                    *(float2*)&ob[(size_t)(c0 + cc) * HW] =
                        make_float2(e0 + o0v, e1 + o1v);
                }

                if (rnd < 7) {
#pragma unroll
                    for (int cc = 0; cc < 2; cc++)
#pragma unroll
                        for (int l = 0; l < 5; l++) {
                            int idx = tid + l * 256;
                            if (idx < 28 * 44) {
                                int r    = idx / 44;
                                int ccol = idx - r * 44;
                                xsb[(((1 - cur) * 2 + cc) * 28 + r) * 48 + ccol]
                                    = pf[cc * 5 + l];
                            }
                        }
                    __syncthreads();
                }
            }
            __syncthreads();   // all reads of xsb done before next unit primes
        }
    }
}

// ---------------------------------------------------------------------------
#define SMEM_DYN (C * 32 * 8 + C * 33 * 8)   // 66560 B (phase-1 layout is largest)

extern "C" void kernel_launch(void* const* d_in, const int* in_sizes, int n_in,
                              void* d_out, int out_size) {
    const float* x   = (const float*)d_in[0];   // [4,128,64,64]
    const float* wr  = (const float*)d_in[1];   // [32,128]
    const float* br  = (const float*)d_in[2];   // [32]
    const float* wsp = (const float*)d_in[3];   // [392,32]
    const float* bsp = (const float*)d_in[4];   // [392]
    float* out = (float*)d_out;

    cudaFuncSetAttribute(k_all, cudaFuncAttributeMaxDynamicSharedMemorySize,
                         SMEM_DYN);

    k_zero_flags<<<1, 256>>>();
    k_all<<<NCTA, 256, SMEM_DYN>>>(x, wr, br, wsp, bsp, out);
}

// round 13
// speedup vs baseline: 1.1107x; 1.1107x over previous
#include <cuda_runtime.h>

#define HW   4096
#define C    128
#define CR   32
#define G    8
#define CG   16
#define KK   49
#define KKG  392
#define NPX  16384   // B * H * W

typedef unsigned long long u64;

// ---- packed f32x2 helpers (sm_103a) ---------------------------------------
__device__ __forceinline__ u64 pack2(float x, float y) {
    u64 r; asm("mov.b64 %0, {%1, %2};" : "=l"(r) : "f"(x), "f"(y)); return r;
}
__device__ __forceinline__ void unpack2(u64 v, float& x, float& y) {
    asm("mov.b64 {%0, %1}, %2;" : "=f"(x), "=f"(y) : "l"(v));
}
__device__ __forceinline__ void ffma2(u64& d, u64 a, u64 b) {
    asm("fma.rn.f32x2 %0, %1, %2, %0;" : "+l"(d) : "l"(a), "l"(b));
}

// Scratch
__device__ __align__(16) float g_ker[4 * KKG * HW];    // [b][392][hw]

// Dynamic smem layout for k_genker (bytes):
//   [0,            33792)  wsd_red : u64[128c][33] (32 o duplicated, stride 33)
//   [33792,        66560)  xsd     : u64[128c][32 px-pairs]   (reused: wsd_span u64[56][32])
//   [66560,        83200)  rs      : float[32k][130] (128 px + even pad)
#define OFF_XSD   33792
#define OFF_RS    66560
#define SMEM_GEN  83200

// ---------------------------------------------------------------------------
// Kernel 1 (genker = reduce fused into span). 128 CTAs (1 wave), 256 thr.
// Phase A: 2 chunks of 64 px: stage x, compute red -> smem rs (no gmem trip).
// Phase B: 7 o-tiles of 56 outs over the resident rs -> g_ker.
// ---------------------------------------------------------------------------
__global__ __launch_bounds__(256) void k_genker(const float* __restrict__ x,
                                                const float* __restrict__ wr,
                                                const float* __restrict__ br,
                                                const float* __restrict__ wsp,
                                                const float* __restrict__ bs) {
    extern __shared__ char smem[];
    u64*   wsd_red = (u64*)smem;                 // [c][33]
    u64*   xsd     = (u64*)(smem + OFF_XSD);     // [c][32]
    u64*   wsd_spn = (u64*)(smem + OFF_XSD);     // reuse after Phase A
    float* rs      = (float*)(smem + OFF_RS);    // [k][130]

    const int tid  = threadIdx.x;
    const int lane = tid & 31;
    const int warp = tid >> 5;
    const int wo   = warp * 4;                   // reduce: warp's 4 out channels
    const int px0  = blockIdx.x * 128;
    const int b    = px0 >> 12;
    const int hw0  = px0 & 4095;

    // stage duplicated w_reduce once
#pragma unroll
    for (int l = 0; l < 16; l++) {
        int idx = tid + l * 256;                 // 4096 = 32 o * 128 c
        int c = idx & 127, o = idx >> 7;
        float v = wr[o * C + c];
        wsd_red[c * 33 + o] = pack2(v, v);
    }

    // ---------------- Phase A: reduce 2 chunks of 64 px into rs ------------
#pragma unroll
    for (int chunk = 0; chunk < 2; chunk++) {
        const float* xb = x + (size_t)b * C * HW + hw0 + chunk * 64;
        __syncthreads();                         // xsd reuse + wsd_red visible
#pragma unroll
        for (int l = 0; l < 16; l++) {
            int idx = tid + l * 256;             // 4096 = 128 c * 32 pairs
            int c = idx >> 5, p2 = idx & 31;
            float2 v = *(const float2*)&xb[(size_t)c * HW + 2 * p2];
            xsd[c * 32 + p2] = pack2(v.x, v.y);
        }
        __syncthreads();

        u64 acc[4];
#pragma unroll
        for (int j = 0; j < 4; j++) {
            float bj = br[wo + j];
            acc[j] = pack2(bj, bj);
        }
#pragma unroll 8
        for (int k = 0; k < C; k++) {
            const u64 a = xsd[k * 32 + lane];
#pragma unroll
            for (int j = 0; j < 4; j++)
                ffma2(acc[j], a, wsd_red[k * 33 + wo + j]);
        }
#pragma unroll
        for (int j = 0; j < 4; j++) {
            float f0, f1; unpack2(acc[j], f0, f1);
            *(float2*)&rs[(wo + j) * 130 + chunk * 64 + 2 * lane] =
                make_float2(f0, f1);
        }
    }

    // ---------------- Phase B: span, 7 o-tiles over resident rs ------------
    for (int ot = 0; ot < 7; ot++) {
        const int o0 = ot * 56;
        __syncthreads();                         // rs done / wsd_spn reuse
#pragma unroll
        for (int l = 0; l < 7; l++) {
            int idx = tid + l * 256;             // 1792 = 56 o * 32 k
            float v = wsp[o0 * 32 + idx];
            wsd_spn[idx] = pack2(v, v);
        }
        __syncthreads();

        u64 acc[2][7];
#pragma unroll
        for (int j = 0; j < 7; j++) {
            float bv = bs[o0 + warp * 7 + j];
            acc[0][j] = pack2(bv, bv);
            acc[1][j] = acc[0][j];
        }

#pragma unroll
        for (int k = 0; k < 32; k++) {
            const u64 a0 = *(const u64*)&rs[k * 130 + 2 * lane];
            const u64 a1 = *(const u64*)&rs[k * 130 + 2 * lane + 64];
#pragma unroll
            for (int j = 0; j < 7; j++) {
                const u64 b2 = wsd_spn[(warp * 7 + j) * 32 + k];  // uniform bcast
                ffma2(acc[0][j], a0, b2);
                ffma2(acc[1][j], a1, b2);
            }
        }

#pragma unroll
        for (int j = 0; j < 7; j++) {
            const int o = o0 + warp * 7 + j;
            float* kp = g_ker + ((size_t)b * KKG + o) * HW + hw0;
            float f0, f1; unpack2(acc[0][j], f0, f1);
            *(float2*)&kp[2 * lane] = make_float2(f0, f1);
            unpack2(acc[1][j], f0, f1);
            *(float2*)&kp[2 * lane + 64] = make_float2(f0, f1);
        }
    }
}

// ---------------------------------------------------------------------------
// Kernel 2: involution — byte-identical to the R11 winner (51.3us run).
// Block 256 (16x16), 32x16 px tile, dual accumulators, ping-pong staging.
// ---------------------------------------------------------------------------
__global__ __launch_bounds__(256) void k_inv(const float* __restrict__ x,
                                             float* __restrict__ out) {
    __shared__ float xs[2][2][28][48];   // [buf][ch][row][col]
    const int tx = threadIdx.x, ty = threadIdx.y;   // (16,16)
    const int tid = ty * 16 + tx;
    const int tx0 = blockIdx.x * 32, ty0 = blockIdx.y * 16;
    const int bg = blockIdx.z;
    const int b = bg >> 3, g = bg & 7;
    const int pix = (ty0 + ty) * 64 + tx0 + 2 * tx;

    const float* kb = g_ker + ((size_t)b * KKG + g * KK) * HW + pix;
    u64 kreg[49];
#pragma unroll
    for (int kk = 0; kk < 49; kk++) kreg[kk] = *(const u64*)&kb[(size_t)kk * HW];

    const float* xb = x + ((size_t)b * C + g * CG) * HW;
    float* ob = out + ((size_t)b * C + g * CG) * HW + pix;

#pragma unroll
    for (int cc = 0; cc < 2; cc++) {
        const float* xc = xb + (size_t)cc * HW;
#pragma unroll
        for (int l = 0; l < 5; l++) {
            int idx = tid + l * 256;
            if (idx < 28 * 44) {
                int r    = idx / 44;
                int ccol = idx - r * 44;
                int gy = ty0 - 6 + r, gx = tx0 - 6 + ccol;
                float v = 0.f;
                if (gy >= 0 && gy < 64 && gx >= 0 && gx < 64)
                    v = xc[gy * 64 + gx];
                xs[0][cc][r][ccol] = v;
            }
        }
    }
    __syncthreads();

    for (int rnd = 0; rnd < 8; rnd++) {
        const int cur = rnd & 1;
        const int c0  = rnd * 2;

        float pf[10];
        if (rnd < 7) {
#pragma unroll
            for (int cc = 0; cc < 2; cc++) {
                const float* xc = xb + (size_t)(c0 + 2 + cc) * HW;
#pragma unroll
                for (int l = 0; l < 5; l++) {
                    int idx = tid + l * 256;
                    float v = 0.f;
                    if (idx < 28 * 44) {
                        int r    = idx / 44;
                        int ccol = idx - r * 44;
                        int gy = ty0 - 6 + r, gx = tx0 - 6 + ccol;
                        if (gy >= 0 && gy < 64 && gx >= 0 && gx < 64)
                            v = xc[gy * 64 + gx];
                    }
                    pf[cc * 5 + l] = v;
                }
            }
        }

#pragma unroll
        for (int cc = 0; cc < 2; cc++) {
            u64 a0 = 0, a1 = 0;
#pragma unroll
            for (int i = 0; i < 7; i++)
#pragma unroll
                for (int j = 0; j < 7; j++) {
                    const int t = i * 7 + j;
                    const u64 v = *(const u64*)&xs[cur][cc][ty + 2 * i][2 * tx + 2 * j];
                    if (t & 1) ffma2(a1, v, kreg[t]);
                    else       ffma2(a0, v, kreg[t]);
                }
            float e0, e1, o0v, o1v;
            unpack2(a0, e0, e1); unpack2(a1, o0v, o1v);
            *(float2*)&ob[(size_t)(c0 + cc) * HW] = make_float2(e0 + o0v, e1 + o1v);
        }

        if (rnd < 7) {
#pragma unroll
            for (int cc = 0; cc < 2; cc++)
#pragma unroll
                for (int l = 0; l < 5; l++) {
                    int idx = tid + l * 256;
                    if (idx < 28 * 44) {
                        int r    = idx / 44;
                        int ccol = idx - r * 44;
                        xs[1 - cur][cc][r][ccol] = pf[cc * 5 + l];
                    }
                }
            __syncthreads();
        }
    }
}

// ---------------------------------------------------------------------------
extern "C" void kernel_launch(void* const* d_in, const int* in_sizes, int n_in,
                              void* d_out, int out_size) {
    const float* x   = (const float*)d_in[0];   // [4,128,64,64]
    const float* wr  = (const float*)d_in[1];   // [32,128]
    const float* br  = (const float*)d_in[2];   // [32]
    const float* wsp = (const float*)d_in[3];   // [392,32]
    const float* bsp = (const float*)d_in[4];   // [392]
    float* out = (float*)d_out;

    cudaFuncSetAttribute(k_genker, cudaFuncAttributeMaxDynamicSharedMemorySize,
                         SMEM_GEN);

    k_genker<<<128, 256, SMEM_GEN>>>(x, wr, br, wsp, bsp);
    k_inv<<<dim3(2, 4, 32), dim3(16, 16)>>>(x, out);
}

// round 14
// speedup vs baseline: 1.1524x; 1.0375x over previous
#include <cuda_runtime.h>

#define HW   4096
#define C    128
#define CR   32
#define G    8
#define CG   16
#define KK   49
#define KKG  392
#define NPX  16384   // B * H * W

typedef unsigned long long u64;

// ---- packed f32x2 helpers (sm_103a) ---------------------------------------
__device__ __forceinline__ u64 pack2(float x, float y) {
    u64 r; asm("mov.b64 %0, {%1, %2};" : "=l"(r) : "f"(x), "f"(y)); return r;
}
__device__ __forceinline__ void unpack2(u64 v, float& x, float& y) {
    asm("mov.b64 {%0, %1}, %2;" : "=f"(x), "=f"(y) : "l"(v));
}
__device__ __forceinline__ void ffma2(u64& d, u64 a, u64 b) {
    asm("fma.rn.f32x2 %0, %1, %2, %0;" : "+l"(d) : "l"(a), "l"(b));
}

// Scratch (16B-aligned)
__device__ __align__(16) float g_red[CR * NPX];        // [k][px]  k-major
__device__ __align__(16) float g_ker[4 * KKG * HW];    // [b][392][hw]

// ---------------------------------------------------------------------------
// Kernel 1: red[k][px] (R11-proven). Block 256, tile 64 px, grid 256.
// ---------------------------------------------------------------------------
__global__ __launch_bounds__(256) void k_reduce(const float* __restrict__ x,
                                                const float* __restrict__ wr,
                                                const float* __restrict__ br) {
    __shared__ u64 xsd[C * 32];        // [c][p2], 32 KB
    __shared__ u64 wsd[C * 33];        // [c][o] duplicated (w,w), stride 33
    const int tid  = threadIdx.x;
    const int lane = tid & 31;
    const int warp = tid >> 5;
    const int px0  = blockIdx.x * 64;
    const int b    = px0 >> 12;
    const int hw0  = px0 & 4095;
    const float* xb = x + (size_t)b * C * HW + hw0;

#pragma unroll
    for (int l = 0; l < 16; l++) {
        int idx = tid + l * 256;
        int c = idx >> 5, p2 = idx & 31;
        float2 v = *(const float2*)&xb[(size_t)c * HW + 2 * p2];
        xsd[c * 32 + p2] = pack2(v.x, v.y);
    }
#pragma unroll
    for (int l = 0; l < 16; l++) {
        int idx = tid + l * 256;
        int c = idx & 127, o = idx >> 7;
        float v = wr[o * C + c];
        wsd[c * 33 + o] = pack2(v, v);
    }
    __syncthreads();

    const int wo = warp * 4;
    u64 acc[4];
#pragma unroll
    for (int j = 0; j < 4; j++) {
        float bj = br[wo + j];
        acc[j] = pack2(bj, bj);
    }
#pragma unroll 8
    for (int k = 0; k < C; k++) {
        const u64 a = xsd[k * 32 + lane];
#pragma unroll
        for (int j = 0; j < 4; j++)
            ffma2(acc[j], a, wsd[k * 33 + wo + j]);
    }
#pragma unroll
    for (int j = 0; j < 4; j++) {
        float f0, f1; unpack2(acc[j], f0, f1);
        *(float2*)&g_red[(size_t)(wo + j) * NPX + px0 + 2 * lane] = make_float2(f0, f1);
    }
}

// ---------------------------------------------------------------------------
// Kernel 2: span (R11-proven shape): 256 px x 56 outs, grid (64,7).
// ---------------------------------------------------------------------------
__global__ __launch_bounds__(256) void k_span(const float* __restrict__ wsp,
                                              const float* __restrict__ bs) {
    __shared__ float rs[CR][258];
    __shared__ float ws[56 * 32];
    const int tid  = threadIdx.x;
    const int lane = tid & 31;
    const int warp = tid >> 5;
    const int px0  = blockIdx.x * 256;
    const int o0   = blockIdx.y * 56;
    const int b    = px0 >> 12;
    const int hw0  = px0 & 4095;

#pragma unroll
    for (int l = 0; l < 32; l++) {
        int idx = tid + l * 256;
        int k = idx >> 8, px = idx & 255;
        rs[k][px] = g_red[(size_t)k * NPX + px0 + px];
    }
#pragma unroll
    for (int l = 0; l < 7; l++) {
        int idx = tid + l * 256;
        ws[idx] = wsp[o0 * 32 + idx];
    }
    __syncthreads();

    u64 acc[4][7] = {};
#pragma unroll
    for (int k = 0; k < 32; k++) {
        u64 a[4];
#pragma unroll
        for (int v = 0; v < 4; v++)
            a[v] = *(const u64*)&rs[k][2 * lane + 64 * v];
#pragma unroll
        for (int j = 0; j < 7; j++) {
            const float bv = ws[(warp * 7 + j) * 32 + k];
            const u64 b2 = pack2(bv, bv);
#pragma unroll
            for (int v = 0; v < 4; v++) ffma2(acc[v][j], a[v], b2);
        }
    }
#pragma unroll
    for (int j = 0; j < 7; j++) {
        const int o = o0 + warp * 7 + j;
        const float bias = bs[o];
        float* kp = g_ker + ((size_t)b * KKG + o) * HW + hw0;
#pragma unroll
        for (int v = 0; v < 4; v++) {
            float f0, f1; unpack2(acc[v][j], f0, f1);
            *(float2*)&kp[2 * lane + 64 * v] = make_float2(f0 + bias, f1 + bias);
        }
    }
}

// ---------------------------------------------------------------------------
// Kernel 3: involution, channels-in-registers. Block 256 (16x16), 32x16 tile.
// All 16 channels staged ONCE into 86KB dynamic smem (2 syncs total).
// Accumulators = 16 channel u64s (32 regs); kernel values streamed 7/row.
// ~70 regs -> 2 CTAs/SM -> 256 CTAs all resident in ONE wave.
// ---------------------------------------------------------------------------
#define SMEM_INV (CG * 28 * 48 * 4)   // 86016 B

__global__ __launch_bounds__(256) void k_inv(const float* __restrict__ x,
                                             float* __restrict__ out) {
    extern __shared__ float xs[];      // [16 ch][28 r][48 c]
    const int tx = threadIdx.x, ty = threadIdx.y;   // (16,16)
    const int tid = ty * 16 + tx;
    const int tx0 = blockIdx.x * 32, ty0 = blockIdx.y * 16;
    const int bg = blockIdx.z;
    const int b = bg >> 3, g = bg & 7;
    const int pix = (ty0 + ty) * 64 + tx0 + 2 * tx;   // even -> 8B aligned

    const float* kb = g_ker + ((size_t)b * KKG + g * KK) * HW + pix;
    const float* xb = x + ((size_t)b * C + g * CG) * HW;
    float* ob = out + ((size_t)b * C + g * CG) * HW + pix;

    // ---- stage all 16 channels (28 x 44 each, row stride 48) --------------
#pragma unroll
    for (int c = 0; c < CG; c++) {
        const float* xc = xb + (size_t)c * HW;
#pragma unroll
        for (int l = 0; l < 5; l++) {
            int idx = tid + l * 256;
            if (idx < 28 * 44) {
                int r    = idx / 44;
                int ccol = idx - r * 44;
                int gy = ty0 - 6 + r, gx = tx0 - 6 + ccol;
                float v = 0.f;
                if (gy >= 0 && gy < 64 && gx >= 0 && gx < 64)
                    v = xc[gy * 64 + gx];
                xs[(c * 28 + r) * 48 + ccol] = v;
            }
        }
    }
    __syncthreads();

    // ---- accumulate: taps outer (kv streamed), channels inner -------------
    u64 acc[CG] = {};

#pragma unroll
    for (int i = 0; i < 7; i++) {
        u64 kv[7];
#pragma unroll
        for (int j = 0; j < 7; j++)
            kv[j] = *(const u64*)&kb[(size_t)(i * 7 + j) * HW];

        const int row = ty + 2 * i;
#pragma unroll
        for (int c = 0; c < CG; c++) {
            const float* bp = &xs[(c * 28 + row) * 48 + 2 * tx];
#pragma unroll
            for (int j = 0; j < 7; j++)
                ffma2(acc[c], *(const u64*)&bp[2 * j], kv[j]);
        }
    }

#pragma unroll
    for (int c = 0; c < CG; c++) {
        float f0, f1; unpack2(acc[c], f0, f1);
        *(float2*)&ob[(size_t)c * HW] = make_float2(f0, f1);
    }
}

// ---------------------------------------------------------------------------
extern "C" void kernel_launch(void* const* d_in, const int* in_sizes, int n_in,
                              void* d_out, int out_size) {
    const float* x   = (const float*)d_in[0];   // [4,128,64,64]
    const float* wr  = (const float*)d_in[1];   // [32,128]
    const float* br  = (const float*)d_in[2];   // [32]
    const float* wsp = (const float*)d_in[3];   // [392,32]
    const float* bsp = (const float*)d_in[4];   // [392]
    float* out = (float*)d_out;

    cudaFuncSetAttribute(k_inv, cudaFuncAttributeMaxDynamicSharedMemorySize,
                         SMEM_INV);

    k_reduce<<<256, 256>>>(x, wr, br);
    k_span<<<dim3(64, 7), 256>>>(wsp, bsp);
    k_inv<<<dim3(2, 4, 32), dim3(16, 16), SMEM_INV>>>(x, out);
}